// round 16
// baseline (speedup 1.0000x reference)
#include <cuda_runtime.h>

#define NN 1024
#define CD 256
#define HH 4
#define FF 64
#define BROWS 32
#define TMm 32
#define NSPLIT 4
#define MPS (NN / NSPLIT)      // m's per split = 256
#define NTILES (MPS / TMm)     // tiles per split = 8
#define WTS 132                // w_t row stride (floats): [m][h*32 + n], pad 4
#define ADJS 36                // adj_s row stride (floats)

typedef unsigned long long ull;
#define ABSM 0x7FFFFFFF7FFFFFFFULL

__device__ __forceinline__ ull fma2(ull a, ull b, ull c) {
    ull d;
    asm("fma.rn.f32x2 %0, %1, %2, %3;" : "=l"(d) : "l"(a), "l"(b), "l"(c));
    return d;
}
__device__ __forceinline__ ull add2(ull a, ull b) {
    ull d;
    asm("add.rn.f32x2 %0, %1, %2;" : "=l"(d) : "l"(a), "l"(b));
    return d;
}
__device__ __forceinline__ ull pack2(float lo, float hi) {
    ull d;
    asm("mov.b64 %0, {%1, %2};" : "=l"(d) : "f"(lo), "f"(hi));
    return d;
}
__device__ __forceinline__ float2 unpack2(ull v) {
    float2 r;
    asm("mov.b64 {%0, %1}, %2;" : "=f"(r.x), "=f"(r.y) : "l"(v));
    return r;
}
__device__ __forceinline__ float hsum2(ull v) {
    float2 r = unpack2(v);
    return r.x + r.y;
}

// scratch (device globals: no allocs allowed)
__device__ float g_gl[NN * CD];
__device__ float g_gr[NN * CD];
__device__ float g_ecl[NN * HH];             // 0.6 * sum_f aw[f]*g_l[m,h,f]
__device__ float g_ecr[NN * HH];             // 0.6 * sum_f aw[f]*g_r[n,h,f]
__device__ float g_pacc[NSPLIT * NN * CD];   // partial numerators
__device__ float g_pden[NSPLIT * NN * HH];   // partial denominators

// gat dynamic-smem layout (tile-pair double structures)
struct GatSmem {
    float sq[BROWS][CD];                     // 32768 B
    ulonglong2 gl2[2][HH][FF / 4][TMm + 1];  // 67584 B
    float w_t[2][TMm][WTS];                  // 33792 B
    float adj_s[2][TMm][ADJS];               //  9216 B
    float ecl_s[2][TMm * HH];                //  1024 B
    float c2s[FF];                           //   256 B
    float ecr_s[BROWS * HH];                 //   512 B
};                                           // ~142 KB

// ------- GEMM (R7 version — measured best): 32x64 tiles, 512 thr, db-buffered -------
__global__ __launch_bounds__(512)
void gemm_kernel(const float* __restrict__ X0, const float* __restrict__ W0,
                 const float* __restrict__ X1, const float* __restrict__ W1,
                 const float* __restrict__ attn_w) {
    const float* X;
    const float* W;
    float* G;
    float* EC;
    if (blockIdx.z == 0) { X = X0; W = W0; G = g_gl; EC = g_ecl; }
    else                 { X = X1; W = W1; G = g_gr; EC = g_ecr; }

    __shared__ __align__(16) float As[2][16][34];   // [buf][k][row]
    __shared__ __align__(16) float Bs[2][16][64];   // [buf][k][col]

    int t = threadIdx.x;
    int bm = blockIdx.y * 32;
    int bn = blockIdx.x * 64;
    int head = blockIdx.x;     // bn = head*64
    int tr = t >> 5;           // warp id 0..15 -> rows 2tr, 2tr+1
    int tc = t & 31;           // lane -> cols 2tc, 2tc+1

    int ar  = t >> 2;            // 0..31 (t<128)
    int ac4 = (t & 3) << 2;
    int bi  = t - 128;           // valid for t in [128,384)
    int br  = bi >> 4;
    int bc4 = (bi & 15) << 2;
    bool doA = (t < 128);
    bool doB = (t >= 128 && t < 384);

    ull acc0 = 0, acc1 = 0;

    float4 av, bv;
    if (doA) av = *(const float4*)(X + (size_t)(bm + ar) * CD + ac4);
    if (doB) bv = *(const float4*)(W + (size_t)br * CD + bn + bc4);
    if (doA) {
        As[0][ac4 + 0][ar] = av.x; As[0][ac4 + 1][ar] = av.y;
        As[0][ac4 + 2][ar] = av.z; As[0][ac4 + 3][ar] = av.w;
    }
    if (doB) *(float4*)&Bs[0][br][bc4] = bv;
    __syncthreads();

    for (int kc = 0; kc < 16; kc++) {
        int cur = kc & 1;
        if (kc < 15) {
            if (doA) av = *(const float4*)(X + (size_t)(bm + ar) * CD + (kc + 1) * 16 + ac4);
            if (doB) bv = *(const float4*)(W + (size_t)((kc + 1) * 16 + br) * CD + bn + bc4);
        }
#pragma unroll
        for (int k = 0; k < 16; k++) {
            float2 a = *(const float2*)&As[cur][k][tr * 2];
            ull b = *(const ull*)&Bs[cur][k][tc * 2];
            acc0 = fma2(pack2(a.x, a.x), b, acc0);
            acc1 = fma2(pack2(a.y, a.y), b, acc1);
        }
        if (kc < 15) {
            int nxt = cur ^ 1;
            if (doA) {
                As[nxt][ac4 + 0][ar] = av.x; As[nxt][ac4 + 1][ar] = av.y;
                As[nxt][ac4 + 2][ar] = av.z; As[nxt][ac4 + 3][ar] = av.w;
            }
            if (doB) *(float4*)&Bs[nxt][br][bc4] = bv;
        }
        __syncthreads();
    }

    *(ull*)&G[(size_t)(bm + tr * 2 + 0) * CD + bn + tc * 2] = acc0;
    *(ull*)&G[(size_t)(bm + tr * 2 + 1) * CD + bn + tc * 2] = acc1;

    {
        float2 awv = *(const float2*)(attn_w + 2 * tc);
        float2 r0 = unpack2(acc0), r1 = unpack2(acc1);
        float s0 = awv.x * r0.x + awv.y * r0.y;
        float s1 = awv.x * r1.x + awv.y * r1.y;
#pragma unroll
        for (int off = 16; off; off >>= 1) {
            s0 += __shfl_xor_sync(0xffffffffu, s0, off);
            s1 += __shfl_xor_sync(0xffffffffu, s1, off);
        }
        if (tc == 0) {
            EC[(size_t)(bm + tr * 2 + 0) * HH + head] = 0.6f * s0;
            EC[(size_t)(bm + tr * 2 + 1) * HH + head] = 0.6f * s1;
        }
    }
}

// ---------------- fused GATv2 attention (m-split partials, f32x2) ----------------
// e[n,m,h] = ecr[n,h] + ecl[m,h] + sum_f c2[f]*|q+g|   (c2 = 0.4*aw)
// BROWS=32, 1024 threads. Tile-PAIR loop: 3 barriers per 2 tiles.
__global__ __launch_bounds__(1024, 1)
void gat_kernel(const float* __restrict__ adj, const float* __restrict__ attn_w) {
    extern __shared__ __align__(16) char gat_smem_raw[];
    GatSmem* S = (GatSmem*)gat_smem_raw;

    int t  = threadIdx.x;
    int n0 = blockIdx.x * BROWS;
    int sp = blockIdx.y;
    int mbase = sp * MPS;

    // load queries (as 16B) + coefficient vector + ecr
    {
        ulonglong2* sq2 = (ulonglong2*)S->sq;
#pragma unroll
        for (int j = 0; j < 2; j++) {
            int i = t + j * 1024;                 // 0 .. 2047
            int r = i >> 6, c2 = i & 63;
            sq2[i] = *(const ulonglong2*)(g_gr + (size_t)(n0 + r) * CD + 4 * c2);
        }
    }
    if (t < FF) S->c2s[t] = 0.4f * attn_w[t];
    else if (t >= 64 && t < 64 + BROWS * HH) S->ecr_s[t - 64] = g_ecr[n0 * HH + (t - 64)];

    int em   = t & 31;
    int wrp  = t >> 5;         // 0..31
    int eh   = wrp & 3;        // head
    int nb   = (wrp >> 2) * 4; // n base within block: 0,4,...,28

    // agg mapping
    int ac  = t & 255;         // output column
    int ah  = ac >> 6;         // head for w_t reads
    int nb8 = (t >> 8) * 8;    // n base (0,8,16,24)

    float dsum[4] = {0.f, 0.f, 0.f, 0.f};
    ull accp[4] = {0ULL, 0ULL, 0ULL, 0ULL};   // n-pairs within my 8-n group

    const ulonglong2* qb  = (const ulonglong2*)&S->sq[nb][eh * FF];  // n stride = 64 ulonglong2
    const ulonglong2* c2p = (const ulonglong2*)S->c2s;

    for (int tp = 0; tp < NTILES / 2; tp++) {
        int m0 = mbase + tp * 2 * TMm;
        __syncthreads();  // previous agg done before overwriting gl2 / w_t

        // load BOTH tiles of the pair: gl2[b][h][fp2][m], b = 0,1
#pragma unroll
        for (int j = 0; j < 4; j++) {
            int i  = t + (j & 1) * 1024;          // 0 .. 2047
            int b  = j >> 1;
            int mm = m0 + b * TMm;
            int m = i >> 6, cc2 = i & 63;
            S->gl2[b][cc2 >> 4][cc2 & 15][m] =
                *(const ulonglong2*)(g_gl + (size_t)(mm + m) * CD + 4 * cc2);
        }
        if (t < TMm * HH) {
            S->ecl_s[0][t] = g_ecl[m0 * HH + t];
            S->ecl_s[1][t] = g_ecl[(m0 + TMm) * HH + t];
        } else if (t < TMm * HH + TMm * 16) {
            int i = t - TMm * HH;      // 0..511 -> 2 bufs x 32 rows x 8 float4
            int b = i >> 8;
            int r = (i >> 3) & 31, hf = (i & 7) * 4;
            *(float4*)&S->adj_s[b][r][hf] =
                *(const float4*)(adj + (size_t)(m0 + b * TMm + r) * NN + n0 + hf);
        }
        __syncthreads();

        // ---- e-phase for both tiles ----
#pragma unroll
        for (int b = 0; b < 2; b++) {
            ull aB0 = 0, aB1 = 0, aB2 = 0, aB3 = 0;
            const ulonglong2* gp = &S->gl2[b][eh][0][em];
#pragma unroll
            for (int fp2 = 0; fp2 < FF / 4; fp2++) {
                ulonglong2 c2v = c2p[fp2];
                ulonglong2 g   = gp[fp2 * (TMm + 1)];
                ull x0, x1;
                ulonglong2 qv;
#define EABS(N, ACC) \
                qv = qb[(N) * 64 + fp2]; \
                x0 = add2(qv.x, g.x); x1 = add2(qv.y, g.y); \
                ACC = fma2(c2v.x, x0 & ABSM, ACC); \
                ACC = fma2(c2v.y, x1 & ABSM, ACC);
                EABS(0, aB0) EABS(1, aB1) EABS(2, aB2) EABS(3, aB3)
#undef EABS
            }
            float base = S->ecl_s[b][em * HH + eh];

            float4 am = *(const float4*)&S->adj_s[b][em][nb];
            float w0 = (am.x != 0.f) ? __expf(hsum2(aB0) + base + S->ecr_s[(nb + 0) * HH + eh]) : 0.f;
            float w1 = (am.y != 0.f) ? __expf(hsum2(aB1) + base + S->ecr_s[(nb + 1) * HH + eh]) : 0.f;
            float w2 = (am.z != 0.f) ? __expf(hsum2(aB2) + base + S->ecr_s[(nb + 2) * HH + eh]) : 0.f;
            float w3 = (am.w != 0.f) ? __expf(hsum2(aB3) + base + S->ecr_s[(nb + 3) * HH + eh]) : 0.f;
            dsum[0] += w0; dsum[1] += w1; dsum[2] += w2; dsum[3] += w3;
            *(float4*)&S->w_t[b][em][eh * 32 + nb] = make_float4(w0, w1, w2, w3);
        }
        __syncthreads();

        // ---- aggregation for both tiles: software-pipelined g prefetch ----
#pragma unroll
        for (int b = 0; b < 2; b++) {
            const float* grp = g_gr + (size_t)(m0 + b * TMm) * CD + ac;
            float gpref[8];
#pragma unroll
            for (int j = 0; j < 8; j++) gpref[j] = __ldg(grp + (size_t)j * CD);
#pragma unroll
            for (int ch = 0; ch < 4; ch++) {
                float gcur[8];
#pragma unroll
                for (int j = 0; j < 8; j++) gcur[j] = gpref[j];
                if (ch < 3) {
#pragma unroll
                    for (int j = 0; j < 8; j++)
                        gpref[j] = __ldg(grp + (size_t)((ch + 1) * 8 + j) * CD);
                }
#pragma unroll
                for (int j = 0; j < 8; j++) {
                    int m = ch * 8 + j;
                    ull gv2 = pack2(gcur[j], gcur[j]);
                    ulonglong2 wa = *(const ulonglong2*)&S->w_t[b][m][ah * 32 + nb8];
                    ulonglong2 wb = *(const ulonglong2*)&S->w_t[b][m][ah * 32 + nb8 + 4];
                    accp[0] = fma2(wa.x, gv2, accp[0]);
                    accp[1] = fma2(wa.y, gv2, accp[1]);
                    accp[2] = fma2(wb.x, gv2, accp[2]);
                    accp[3] = fma2(wb.y, gv2, accp[3]);
                }
            }
        }
    }

    // reduce dsum over lanes (lanes = m slices) -> partial denominators
    {
#pragma unroll
        for (int off = 16; off; off >>= 1) {
#pragma unroll
            for (int i = 0; i < 4; i++)
                dsum[i] += __shfl_xor_sync(0xffffffffu, dsum[i], off);
        }
        if (em == 0) {
#pragma unroll
            for (int i = 0; i < 4; i++)
                g_pden[((size_t)sp * NN + n0 + nb + i) * HH + eh] = dsum[i];
        }
    }

    // partial numerators (8 n's per thread, column ac)
#pragma unroll
    for (int np = 0; np < 4; np++) {
        float2 v = unpack2(accp[np]);
        g_pacc[((size_t)sp * NN + n0 + nb8 + 2 * np + 0) * CD + ac] = v.x;
        g_pacc[((size_t)sp * NN + n0 + nb8 + 2 * np + 1) * CD + ac] = v.y;
    }
}

// ---------------- combine partials + elu (float4) ----------------
__global__ __launch_bounds__(256)
void combine_kernel(const int* __restrict__ use_elu_p, float* __restrict__ out) {
    int idx = blockIdx.x * 256 + threadIdx.x;        // 0 .. 65535 (float4 slots)
    int n   = idx >> 6;
    int c4  = idx & 63;                              // float4 column
    int h   = c4 >> 4;
    float4 a = make_float4(0.f, 0.f, 0.f, 0.f);
    float  d = 0.f;
#pragma unroll
    for (int sp = 0; sp < NSPLIT; sp++) {
        float4 p = *(const float4*)&g_pacc[((size_t)sp * NN + n) * CD + 4 * c4];
        a.x += p.x; a.y += p.y; a.z += p.z; a.w += p.w;
        d += g_pden[((size_t)sp * NN + n) * HH + h];
    }
    float inv = 1.f / d;
    float4 v = make_float4(a.x * inv, a.y * inv, a.z * inv, a.w * inv);
    if (*use_elu_p) {
        v.x = (v.x > 0.f) ? v.x : expm1f(v.x);
        v.y = (v.y > 0.f) ? v.y : expm1f(v.y);
        v.z = (v.z > 0.f) ? v.z : expm1f(v.z);
        v.w = (v.w > 0.f) ? v.w : expm1f(v.w);
    }
    *(float4*)&out[(size_t)n * CD + 4 * c4] = v;
}

extern "C" void kernel_launch(void* const* d_in, const int* in_sizes, int n_in,
                              void* d_out, int out_size) {
    const float* h    = (const float*)d_in[0];
    const float* nei  = (const float*)d_in[1];
    const float* adj  = (const float*)d_in[2];
    const float* w_l  = (const float*)d_in[3];
    const float* w_r  = (const float*)d_in[4];
    const float* aw   = (const float*)d_in[5];
    const int*   uelu = (const int*)d_in[6];
    float* out = (float*)d_out;

    // idempotent attribute set; capture-safe (not a stream op)
    cudaFuncSetAttribute(gat_kernel,
                         cudaFuncAttributeMaxDynamicSharedMemorySize,
                         (int)sizeof(GatSmem));

    dim3 ggrid(CD / 64, NN / 32, 2);
    gemm_kernel<<<ggrid, 512>>>(h, w_l, nei, w_r, aw);
    dim3 agrid(NN / BROWS, NSPLIT);
    gat_kernel<<<agrid, 1024, sizeof(GatSmem)>>>(adj, aw);
    combine_kernel<<<NN * CD / 4 / 256, 256>>>(uelu, out);
}

// round 17
// speedup vs baseline: 2.4451x; 2.4451x over previous
#include <cuda_runtime.h>

#define NN 1024
#define CD 256
#define HH 4
#define FF 64
#define BROWS 32
#define TMm 32
#define NSPLIT 4
#define MPS (NN / NSPLIT)      // m's per split = 256
#define NTILES (MPS / TMm)     // tiles per split = 8
#define WTS 132                // w_t row stride (floats): [m][h*32 + n], pad 4
#define ADJS 36                // adj_s row stride (floats)

typedef unsigned long long ull;
#define ABSM 0x7FFFFFFF7FFFFFFFULL

__device__ __forceinline__ ull fma2(ull a, ull b, ull c) {
    ull d;
    asm("fma.rn.f32x2 %0, %1, %2, %3;" : "=l"(d) : "l"(a), "l"(b), "l"(c));
    return d;
}
__device__ __forceinline__ ull add2(ull a, ull b) {
    ull d;
    asm("add.rn.f32x2 %0, %1, %2;" : "=l"(d) : "l"(a), "l"(b));
    return d;
}
__device__ __forceinline__ ull pack2(float lo, float hi) {
    ull d;
    asm("mov.b64 %0, {%1, %2};" : "=l"(d) : "f"(lo), "f"(hi));
    return d;
}
__device__ __forceinline__ float2 unpack2(ull v) {
    float2 r;
    asm("mov.b64 {%0, %1}, %2;" : "=f"(r.x), "=f"(r.y) : "l"(v));
    return r;
}
__device__ __forceinline__ float hsum2(ull v) {
    float2 r = unpack2(v);
    return r.x + r.y;
}

// scratch (device globals: no allocs allowed)
__device__ float g_gl[NN * CD];
__device__ float g_gr[NN * CD];
__device__ float g_ecl[NN * HH];             // 0.6 * sum_f aw[f]*g_l[m,h,f]
__device__ float g_ecr[NN * HH];             // 0.6 * sum_f aw[f]*g_r[n,h,f]
__device__ float g_pacc[NSPLIT * NN * CD];   // partial numerators
__device__ float g_pden[NSPLIT * NN * HH];   // partial denominators

// gat dynamic-smem layout (R13)
struct GatSmem {
    float sq[BROWS][CD];                     // 32768 B
    ulonglong2 gl2[HH][FF / 4][TMm + 1];     // 33792 B
    float w_t[TMm][WTS];                     // 16896 B
    float adj_s[TMm][ADJS];                  //  4608 B
    float c2s[FF];
    float ecr_s[BROWS * HH];
    float ecl_s[TMm * HH];
};                                           // ~89.3 KB

// ------- GEMM: 64x64 tiles, 512 thr, 4r x 2c per thread, double-buffered -------
// Per k per thread: 1 LDS.128 A (4 rows, warp-uniform) + 1 LDS.64 B (2 cols)
// + 4 pack + 4 fma2 = 10 instr / 8 MACs. Grid (4, 16, 2) = 128 CTAs, 1 wave.
__global__ __launch_bounds__(512)
void gemm_kernel(const float* __restrict__ X0, const float* __restrict__ W0,
                 const float* __restrict__ X1, const float* __restrict__ W1,
                 const float* __restrict__ attn_w) {
    const float* X;
    const float* W;
    float* G;
    float* EC;
    if (blockIdx.z == 0) { X = X0; W = W0; G = g_gl; EC = g_ecl; }
    else                 { X = X1; W = W1; G = g_gr; EC = g_ecr; }

    __shared__ __align__(16) float As[2][16][68];   // [buf][k][row], 272B rows (16B-aligned)
    __shared__ __align__(16) float Bs[2][16][64];   // [buf][k][col]

    int t = threadIdx.x;
    int bm = blockIdx.y * 64;
    int bn = blockIdx.x * 64;
    int head = blockIdx.x;     // bn = head*64
    int tr = t >> 5;           // warp id 0..15 -> rows 4tr .. 4tr+3
    int tc = t & 31;           // lane -> cols 2tc, 2tc+1

    // loader indices
    int ar  = t >> 2;            // 0..63 (t<256): A rows
    int ac4 = (t & 3) << 2;      // 0,4,8,12
    int bi  = t - 256;           // valid for t in [256,512)
    int br  = bi >> 4;           // 0..15
    int bc4 = (bi & 15) << 2;    // 0..60
    bool doA = (t < 256);
    bool doB = (t >= 256);

    ull acc0 = 0, acc1 = 0, acc2 = 0, acc3 = 0;

    float4 av, bv;
    if (doA) av = *(const float4*)(X + (size_t)(bm + ar) * CD + ac4);
    if (doB) bv = *(const float4*)(W + (size_t)br * CD + bn + bc4);
    if (doA) {
        As[0][ac4 + 0][ar] = av.x; As[0][ac4 + 1][ar] = av.y;
        As[0][ac4 + 2][ar] = av.z; As[0][ac4 + 3][ar] = av.w;
    }
    if (doB) *(float4*)&Bs[0][br][bc4] = bv;
    __syncthreads();

    for (int kc = 0; kc < 16; kc++) {
        int cur = kc & 1;
        if (kc < 15) {
            if (doA) av = *(const float4*)(X + (size_t)(bm + ar) * CD + (kc + 1) * 16 + ac4);
            if (doB) bv = *(const float4*)(W + (size_t)((kc + 1) * 16 + br) * CD + bn + bc4);
        }
#pragma unroll
        for (int k = 0; k < 16; k++) {
            float4 a = *(const float4*)&As[cur][k][tr * 4];   // warp-uniform broadcast
            ull b = *(const ull*)&Bs[cur][k][tc * 2];
            acc0 = fma2(pack2(a.x, a.x), b, acc0);
            acc1 = fma2(pack2(a.y, a.y), b, acc1);
            acc2 = fma2(pack2(a.z, a.z), b, acc2);
            acc3 = fma2(pack2(a.w, a.w), b, acc3);
        }
        if (kc < 15) {
            int nxt = cur ^ 1;
            if (doA) {
                As[nxt][ac4 + 0][ar] = av.x; As[nxt][ac4 + 1][ar] = av.y;
                As[nxt][ac4 + 2][ar] = av.z; As[nxt][ac4 + 3][ar] = av.w;
            }
            if (doB) *(float4*)&Bs[nxt][br][bc4] = bv;
        }
        __syncthreads();
    }

    *(ull*)&G[(size_t)(bm + tr * 4 + 0) * CD + bn + tc * 2] = acc0;
    *(ull*)&G[(size_t)(bm + tr * 4 + 1) * CD + bn + tc * 2] = acc1;
    *(ull*)&G[(size_t)(bm + tr * 4 + 2) * CD + bn + tc * 2] = acc2;
    *(ull*)&G[(size_t)(bm + tr * 4 + 3) * CD + bn + tc * 2] = acc3;

    // ---- ec epilogue: warp-reduce aw-weighted row sums ----
    {
        float2 awv = *(const float2*)(attn_w + 2 * tc);
        float2 r0 = unpack2(acc0), r1 = unpack2(acc1);
        float2 r2 = unpack2(acc2), r3 = unpack2(acc3);
        float s0 = awv.x * r0.x + awv.y * r0.y;
        float s1 = awv.x * r1.x + awv.y * r1.y;
        float s2 = awv.x * r2.x + awv.y * r2.y;
        float s3 = awv.x * r3.x + awv.y * r3.y;
#pragma unroll
        for (int off = 16; off; off >>= 1) {
            s0 += __shfl_xor_sync(0xffffffffu, s0, off);
            s1 += __shfl_xor_sync(0xffffffffu, s1, off);
            s2 += __shfl_xor_sync(0xffffffffu, s2, off);
            s3 += __shfl_xor_sync(0xffffffffu, s3, off);
        }
        if (tc == 0) {
            EC[(size_t)(bm + tr * 4 + 0) * HH + head] = 0.6f * s0;
            EC[(size_t)(bm + tr * 4 + 1) * HH + head] = 0.6f * s1;
            EC[(size_t)(bm + tr * 4 + 2) * HH + head] = 0.6f * s2;
            EC[(size_t)(bm + tr * 4 + 3) * HH + head] = 0.6f * s3;
        }
    }
}

// ---------------- fused GATv2 attention (R13 — measured best) ----------------
// e[n,m,h] = ecr[n,h] + ecl[m,h] + sum_f c2[f]*|q+g|   (c2 = 0.4*aw)
// BROWS=32, 1024 threads, 3 barriers/tile.
__global__ __launch_bounds__(1024, 1)
void gat_kernel(const float* __restrict__ adj, const float* __restrict__ attn_w) {
    extern __shared__ __align__(16) char gat_smem_raw[];
    GatSmem* S = (GatSmem*)gat_smem_raw;

    int t  = threadIdx.x;
    int n0 = blockIdx.x * BROWS;
    int sp = blockIdx.y;
    int mbase = sp * MPS;

    // load queries (as 16B) + coefficient vector + ecr
    {
        ulonglong2* sq2 = (ulonglong2*)S->sq;
#pragma unroll
        for (int j = 0; j < 2; j++) {
            int i = t + j * 1024;                 // 0 .. 2047
            int r = i >> 6, c2 = i & 63;
            sq2[i] = *(const ulonglong2*)(g_gr + (size_t)(n0 + r) * CD + 4 * c2);
        }
    }
    if (t < FF) S->c2s[t] = 0.4f * attn_w[t];
    else if (t >= 64 && t < 64 + BROWS * HH) S->ecr_s[t - 64] = g_ecr[n0 * HH + (t - 64)];
    __syncthreads();

    int em   = t & 31;
    int wrp  = t >> 5;         // 0..31
    int eh   = wrp & 3;        // head
    int nb   = (wrp >> 2) * 4; // n base within block: 0,4,...,28

    // agg mapping
    int ac  = t & 255;         // output column
    int ah  = ac >> 6;         // head for w_t reads
    int nb8 = (t >> 8) * 8;    // n base (0,8,16,24)

    // hoist ecr for my 4 n's into registers (constant across tiles)
    float ecr0 = S->ecr_s[(nb + 0) * HH + eh];
    float ecr1 = S->ecr_s[(nb + 1) * HH + eh];
    float ecr2 = S->ecr_s[(nb + 2) * HH + eh];
    float ecr3 = S->ecr_s[(nb + 3) * HH + eh];

    float dsum[4] = {0.f, 0.f, 0.f, 0.f};
    ull accp[4] = {0ULL, 0ULL, 0ULL, 0ULL};   // n-pairs within my 8-n group

    const ulonglong2* qb  = (const ulonglong2*)&S->sq[nb][eh * FF];  // n stride = 64 ulonglong2
    const ulonglong2* c2p = (const ulonglong2*)S->c2s;

    for (int tile = 0; tile < NTILES; tile++) {
        int m0 = mbase + tile * TMm;
        __syncthreads();  // previous agg done before overwriting gl2 / w_t

        // load g_l tile as 16B groups: gl2[h][fp2][m]; plus ecl + adj tiles
#pragma unroll
        for (int j = 0; j < 2; j++) {
            int i = t + j * 1024;                 // 0 .. 2047
            int m = i >> 6, cc2 = i & 63;
            S->gl2[cc2 >> 4][cc2 & 15][m] =
                *(const ulonglong2*)(g_gl + (size_t)(m0 + m) * CD + 4 * cc2);
        }
        if (t < TMm * HH) S->ecl_s[t] = g_ecl[m0 * HH + t];
        else if (t < TMm * HH + TMm * 8) {
            int i = t - TMm * HH;      // 0..255 -> 32 rows x 8 float4
            int row = i >> 3, hf = (i & 7) * 4;
            *(float4*)&S->adj_s[row][hf] =
                *(const float4*)(adj + (size_t)(m0 + row) * NN + n0 + hf);
        }
        __syncthreads();

        // ---- e-phase: e[n0+nb .. +3, m0+em, eh] ----
        {
            ull aB0 = 0, aB1 = 0, aB2 = 0, aB3 = 0;
            const ulonglong2* gp = &S->gl2[eh][0][em];
#pragma unroll
            for (int fp2 = 0; fp2 < FF / 4; fp2++) {
                ulonglong2 c2v = c2p[fp2];
                ulonglong2 g   = gp[fp2 * (TMm + 1)];
                ull x0, x1;
                ulonglong2 qv;
#define EABS(N, ACC) \
                qv = qb[(N) * 64 + fp2]; \
                x0 = add2(qv.x, g.x); x1 = add2(qv.y, g.y); \
                ACC = fma2(c2v.x, x0 & ABSM, ACC); \
                ACC = fma2(c2v.y, x1 & ABSM, ACC);
                EABS(0, aB0) EABS(1, aB1) EABS(2, aB2) EABS(3, aB3)
#undef EABS
            }
            float base = S->ecl_s[em * HH + eh];

            float4 am = *(const float4*)&S->adj_s[em][nb];
            float w0 = (am.x != 0.f) ? __expf(hsum2(aB0) + base + ecr0) : 0.f;
            float w1 = (am.y != 0.f) ? __expf(hsum2(aB1) + base + ecr1) : 0.f;
            float w2 = (am.z != 0.f) ? __expf(hsum2(aB2) + base + ecr2) : 0.f;
            float w3 = (am.w != 0.f) ? __expf(hsum2(aB3) + base + ecr3) : 0.f;
            dsum[0] += w0; dsum[1] += w1; dsum[2] += w2; dsum[3] += w3;
            *(float4*)&S->w_t[em][eh * 32 + nb] = make_float4(w0, w1, w2, w3);
        }
        __syncthreads();

        // ---- aggregation: software-pipelined g prefetch (MLP=8) ----
        const float* grp = g_gr + (size_t)m0 * CD + ac;
        float gpref[8];
#pragma unroll
        for (int j = 0; j < 8; j++) gpref[j] = __ldg(grp + (size_t)j * CD);
#pragma unroll
        for (int ch = 0; ch < 4; ch++) {
            float gcur[8];
#pragma unroll
            for (int j = 0; j < 8; j++) gcur[j] = gpref[j];
            if (ch < 3) {
#pragma unroll
                for (int j = 0; j < 8; j++)
                    gpref[j] = __ldg(grp + (size_t)((ch + 1) * 8 + j) * CD);
            }
#pragma unroll
            for (int j = 0; j < 8; j++) {
                int m = ch * 8 + j;
                ull gv2 = pack2(gcur[j], gcur[j]);
                ulonglong2 wa = *(const ulonglong2*)&S->w_t[m][ah * 32 + nb8];
                ulonglong2 wb = *(const ulonglong2*)&S->w_t[m][ah * 32 + nb8 + 4];
                accp[0] = fma2(wa.x, gv2, accp[0]);
                accp[1] = fma2(wa.y, gv2, accp[1]);
                accp[2] = fma2(wb.x, gv2, accp[2]);
                accp[3] = fma2(wb.y, gv2, accp[3]);
            }
        }
    }

    // reduce dsum over lanes (lanes = m slices) -> partial denominators
    {
#pragma unroll
        for (int off = 16; off; off >>= 1) {
#pragma unroll
            for (int i = 0; i < 4; i++)
                dsum[i] += __shfl_xor_sync(0xffffffffu, dsum[i], off);
        }
        if (em == 0) {
#pragma unroll
            for (int i = 0; i < 4; i++)
                g_pden[((size_t)sp * NN + n0 + nb + i) * HH + eh] = dsum[i];
        }
    }

    // partial numerators (8 n's per thread, column ac)
#pragma unroll
    for (int np = 0; np < 4; np++) {
        float2 v = unpack2(accp[np]);
        g_pacc[((size_t)sp * NN + n0 + nb8 + 2 * np + 0) * CD + ac] = v.x;
        g_pacc[((size_t)sp * NN + n0 + nb8 + 2 * np + 1) * CD + ac] = v.y;
    }
}

// ---------------- combine partials + elu (float4) ----------------
__global__ __launch_bounds__(256)
void combine_kernel(const int* __restrict__ use_elu_p, float* __restrict__ out) {
    int idx = blockIdx.x * 256 + threadIdx.x;        // 0 .. 65535 (float4 slots)
    int n   = idx >> 6;
    int c4  = idx & 63;                              // float4 column
    int h   = c4 >> 4;
    float4 a = make_float4(0.f, 0.f, 0.f, 0.f);
    float  d = 0.f;
#pragma unroll
    for (int sp = 0; sp < NSPLIT; sp++) {
        float4 p = *(const float4*)&g_pacc[((size_t)sp * NN + n) * CD + 4 * c4];
        a.x += p.x; a.y += p.y; a.z += p.z; a.w += p.w;
        d += g_pden[((size_t)sp * NN + n) * HH + h];
    }
    float inv = 1.f / d;
    float4 v = make_float4(a.x * inv, a.y * inv, a.z * inv, a.w * inv);
    if (*use_elu_p) {
        v.x = (v.x > 0.f) ? v.x : expm1f(v.x);
        v.y = (v.y > 0.f) ? v.y : expm1f(v.y);
        v.z = (v.z > 0.f) ? v.z : expm1f(v.z);
        v.w = (v.w > 0.f) ? v.w : expm1f(v.w);
    }
    *(float4*)&out[(size_t)n * CD + 4 * c4] = v;
}

extern "C" void kernel_launch(void* const* d_in, const int* in_sizes, int n_in,
                              void* d_out, int out_size) {
    const float* h    = (const float*)d_in[0];
    const float* nei  = (const float*)d_in[1];
    const float* adj  = (const float*)d_in[2];
    const float* w_l  = (const float*)d_in[3];
    const float* w_r  = (const float*)d_in[4];
    const float* aw   = (const float*)d_in[5];
    const int*   uelu = (const int*)d_in[6];
    float* out = (float*)d_out;

    // idempotent attribute set; capture-safe (not a stream op)
    cudaFuncSetAttribute(gat_kernel,
                         cudaFuncAttributeMaxDynamicSharedMemorySize,
                         (int)sizeof(GatSmem));

    dim3 ggrid(CD / 64, NN / 64, 2);
    gemm_kernel<<<ggrid, 512>>>(h, w_l, nei, w_r, aw);
    dim3 agrid(NN / BROWS, NSPLIT);
    gat_kernel<<<agrid, 1024, sizeof(GatSmem)>>>(adj, aw);
    combine_kernel<<<NN * CD / 4 / 256, 256>>>(uelu, out);
}